// round 1
// baseline (speedup 1.0000x reference)
#include <cuda_runtime.h>
#include <cuda_bf16.h>
#include <cstdint>

// Problem constants: GPT-2 small attention
// x: [1, 8, 1024, 768] -> [M=8192, C=768]
// w_attn: [768, 2304], b_attn: [2304]
// w_proj: [768, 768],  b_proj: [768]
// H = 12 heads, D = 64 head dim
#define BATCH 8
#define SEQ   1024
#define CH    768
#define NH    12
#define HD    64
#define M_ROWS (BATCH * SEQ)      // 8192
#define QKV_N (3 * CH)            // 2304

// Scratch (allocation-free rule: __device__ globals)
__device__ float g_qkv[M_ROWS * QKV_N];   // [8192, 2304]
__device__ float g_att[M_ROWS * CH];      // [8192, 768]  (heads re-interleaved)

// ---------------------------------------------------------------------------
// Tiled SGEMM with bias: C[M,N] = A[M,K] @ B[K,N] + bias[N]
// BM=128, BN=128, BK=8, 256 threads, 8x8 per-thread microtile.
// Assumes M%128==0, N%128==0, K%8==0 (true for all three GEMMs here).
// ---------------------------------------------------------------------------
template <int BM, int BN, int BK, int TM, int TN>
__global__ __launch_bounds__(256) void sgemm_bias_kernel(
    const float* __restrict__ A, const float* __restrict__ B,
    const float* __restrict__ bias, float* __restrict__ C,
    int M, int N, int K)
{
    __shared__ float As[BK][BM + 4];   // +4 pad: conflict-free stores, 16B-aligned rows
    __shared__ float Bs[BK][BN];

    const int tid = threadIdx.x;
    const int tx = tid % (BN / TN);    // 0..15
    const int ty = tid / (BN / TN);    // 0..15
    const int m0 = blockIdx.y * BM;
    const int n0 = blockIdx.x * BN;

    float acc[TM][TN];
#pragma unroll
    for (int i = 0; i < TM; i++)
#pragma unroll
        for (int j = 0; j < TN; j++) acc[i][j] = 0.f;

    for (int k0 = 0; k0 < K; k0 += BK) {
        // Load A tile (BM x BK), store transposed into As
#pragma unroll
        for (int i = 0; i < (BM * BK) / 256; i++) {
            int idx = tid + i * 256;
            int r = idx / BK, c = idx % BK;
            As[c][r] = A[(size_t)(m0 + r) * K + k0 + c];
        }
        // Load B tile (BK x BN) coalesced
#pragma unroll
        for (int i = 0; i < (BK * BN) / 256; i++) {
            int idx = tid + i * 256;
            int r = idx / BN, c = idx % BN;
            Bs[r][c] = B[(size_t)(k0 + r) * N + n0 + c];
        }
        __syncthreads();

#pragma unroll
        for (int k = 0; k < BK; k++) {
            float ra[TM], rb[TN];
            const float4* ap = (const float4*)&As[k][ty * TM];
            const float4* bp = (const float4*)&Bs[k][tx * TN];
#pragma unroll
            for (int v = 0; v < TM / 4; v++) {
                float4 t = ap[v];
                ra[v * 4 + 0] = t.x; ra[v * 4 + 1] = t.y;
                ra[v * 4 + 2] = t.z; ra[v * 4 + 3] = t.w;
            }
#pragma unroll
            for (int v = 0; v < TN / 4; v++) {
                float4 t = bp[v];
                rb[v * 4 + 0] = t.x; rb[v * 4 + 1] = t.y;
                rb[v * 4 + 2] = t.z; rb[v * 4 + 3] = t.w;
            }
#pragma unroll
            for (int i = 0; i < TM; i++)
#pragma unroll
                for (int j = 0; j < TN; j++)
                    acc[i][j] = fmaf(ra[i], rb[j], acc[i][j]);
        }
        __syncthreads();
    }

#pragma unroll
    for (int i = 0; i < TM; i++) {
        int m = m0 + ty * TM + i;
#pragma unroll
        for (int j = 0; j < TN; j++) {
            int n = n0 + tx * TN + j;
            C[(size_t)m * N + n] = acc[i][j] + bias[n];
        }
    }
}

// ---------------------------------------------------------------------------
// Flash attention (fp32, online softmax).
// Grid: (SEQ/BM, NH, BATCH), Block: 128 threads; thread t owns query row q0+t.
// K/V tiles of 64 rows x 64 cols staged in smem (broadcast reads -> no conflicts).
// Causal masking with chunk-level skipping.
// Reads qkv[row, h*64 + {0,768,1536}..], writes att[row, h*64..] (head-interleaved).
// ---------------------------------------------------------------------------
__global__ __launch_bounds__(128) void flash_attn_kernel(
    const float* __restrict__ qkv, float* __restrict__ att)
{
    constexpr int BM = 128;   // queries per block
    constexpr int BN = 64;    // keys per smem tile

    __shared__ float Ks[BN][HD];
    __shared__ float Vs[BN][HD];

    const int tid = threadIdx.x;
    const int qt = blockIdx.x;
    const int h  = blockIdx.y;
    const int b  = blockIdx.z;
    const int qrow = qt * BM + tid;           // query index within sequence

    // Load this thread's q row (scaled by 1/sqrt(D))
    const float* qptr = qkv + (size_t)(b * SEQ + qrow) * QKV_N + h * HD;
    float q[HD];
#pragma unroll
    for (int d = 0; d < HD; d++) q[d] = qptr[d] * 0.125f;

    float o[HD];
#pragma unroll
    for (int d = 0; d < HD; d++) o[d] = 0.f;
    float m = -1e30f, l = 0.f;

    const int ktiles = (qt * BM + BM - 1) / BN + 1;   // tiles needed by max qrow in block

    for (int kt = 0; kt < ktiles; kt++) {
        const float* kbase = qkv + (size_t)(b * SEQ + kt * BN) * QKV_N + CH + h * HD;
        const float* vbase = kbase + CH;

        __syncthreads();   // previous tile fully consumed
#pragma unroll
        for (int i = 0; i < 8; i++) {
            int idx = tid + i * 128;       // 0..1023
            int r = idx >> 4;              // 0..63
            int c4 = idx & 15;             // float4 index 0..15
            ((float4*)&Ks[r][0])[c4] = ((const float4*)(kbase + (size_t)r * QKV_N))[c4];
            ((float4*)&Vs[r][0])[c4] = ((const float4*)(vbase + (size_t)r * QKV_N))[c4];
        }
        __syncthreads();

        // Number of 8-key chunks this thread needs (causal)
        int nch = 0;
        if (qrow >= kt * BN) {
            int last = qrow - kt * BN;            // highest valid key offset in tile
            nch = min(8, (last >> 3) + 1);
        }

        for (int jj = 0; jj < nch; jj++) {
            const int kfirst = kt * BN + jj * 8;

            // scores for 8 keys
            float s[8];
#pragma unroll
            for (int j = 0; j < 8; j++) {
                const float4* kr = (const float4*)&Ks[jj * 8 + j][0];
                float a0 = 0.f, a1 = 0.f, a2 = 0.f, a3 = 0.f;
#pragma unroll
                for (int d4 = 0; d4 < 16; d4++) {
                    float4 kv = kr[d4];
                    a0 = fmaf(q[d4 * 4 + 0], kv.x, a0);
                    a1 = fmaf(q[d4 * 4 + 1], kv.y, a1);
                    a2 = fmaf(q[d4 * 4 + 2], kv.z, a2);
                    a3 = fmaf(q[d4 * 4 + 3], kv.w, a3);
                }
                s[j] = (a0 + a1) + (a2 + a3);
            }

            // causal mask within chunk
#pragma unroll
            for (int j = 0; j < 8; j++)
                if (kfirst + j > qrow) s[j] = -1e30f;

            // online softmax update
            float mc = s[0];
#pragma unroll
            for (int j = 1; j < 8; j++) mc = fmaxf(mc, s[j]);
            float m_new = fmaxf(m, mc);
            float corr = __expf(m - m_new);
            float p[8], psum = 0.f;
#pragma unroll
            for (int j = 0; j < 8; j++) {
                p[j] = __expf(s[j] - m_new);
                psum += p[j];
            }
            l = l * corr + psum;
            m = m_new;

#pragma unroll
            for (int d = 0; d < HD; d++) o[d] *= corr;
#pragma unroll
            for (int j = 0; j < 8; j++) {
                const float4* vr = (const float4*)&Vs[jj * 8 + j][0];
                float pj = p[j];
#pragma unroll
                for (int d4 = 0; d4 < 16; d4++) {
                    float4 vv = vr[d4];
                    o[d4 * 4 + 0] = fmaf(pj, vv.x, o[d4 * 4 + 0]);
                    o[d4 * 4 + 1] = fmaf(pj, vv.y, o[d4 * 4 + 1]);
                    o[d4 * 4 + 2] = fmaf(pj, vv.z, o[d4 * 4 + 2]);
                    o[d4 * 4 + 3] = fmaf(pj, vv.w, o[d4 * 4 + 3]);
                }
            }
        }
    }

    const float inv_l = 1.f / l;
    float* optr = att + (size_t)(b * SEQ + qrow) * CH + h * HD;
#pragma unroll
    for (int d = 0; d < HD; d++) optr[d] = o[d] * inv_l;
}

// ---------------------------------------------------------------------------
// Launch
// ---------------------------------------------------------------------------
extern "C" void kernel_launch(void* const* d_in, const int* in_sizes, int n_in,
                              void* d_out, int out_size)
{
    const float* x      = (const float*)d_in[0];
    const float* w_attn = (const float*)d_in[1];
    const float* b_attn = (const float*)d_in[2];
    const float* w_proj = (const float*)d_in[3];
    const float* b_proj = (const float*)d_in[4];
    float* out = (float*)d_out;

    float* qkv = nullptr;
    float* att = nullptr;
    cudaGetSymbolAddress((void**)&qkv, g_qkv);
    cudaGetSymbolAddress((void**)&att, g_att);

    // 1) QKV GEMM: [8192,768] @ [768,2304] + b_attn
    {
        dim3 grid(QKV_N / 128, M_ROWS / 128);
        sgemm_bias_kernel<128, 128, 8, 8, 8><<<grid, 256>>>(
            x, w_attn, b_attn, qkv, M_ROWS, QKV_N, CH);
    }

    // 2) Flash attention -> att [8192, 768]
    {
        dim3 grid(SEQ / 128, NH, BATCH);
        flash_attn_kernel<<<grid, 128>>>(qkv, att);
    }

    // 3) Output projection: [8192,768] @ [768,768] + b_proj -> out
    {
        dim3 grid(CH / 128, M_ROWS / 128);
        sgemm_bias_kernel<128, 128, 8, 8, 8><<<grid, 256>>>(
            att, w_proj, b_proj, out, M_ROWS, CH, CH);
    }
}

// round 2
// speedup vs baseline: 1.6825x; 1.6825x over previous
#include <cuda_runtime.h>
#include <cuda_bf16.h>
#include <cstdint>

// GPT-2 small attention: x[1,8,1024,768], w_attn[768,2304], w_proj[768,768]
#define BATCH 8
#define SEQ   1024
#define CH    768
#define NH    12
#define HD    64
#define M_ROWS (BATCH * SEQ)      // 8192
#define QKV_N (3 * CH)            // 2304

// Scratch (allocation-free rule: __device__ globals)
__device__ float g_qkv[M_ROWS * QKV_N];   // [8192, 2304]
__device__ float g_att[M_ROWS * CH];      // [8192, 768]

// ---- packed f32x2 helpers (sm_103a FFMA2 path; ptxas never emits these from C++) ----
#define FMA2(d, a, b) asm("fma.rn.f32x2 %0, %1, %2, %0;" : "+l"(d) : "l"(a), "l"(b))
#define MUL2(d, a, b) asm("mul.rn.f32x2 %0, %1, %2;" : "=l"(d) : "l"(a), "l"(b))
#define PACK2(d, lo, hi) asm("mov.b64 %0, {%1, %2};" : "=l"(d) : "f"(lo), "f"(hi))
#define UNPACK2(lo, hi, v) asm("mov.b64 {%0, %1}, %2;" : "=f"(lo), "=f"(hi) : "l"(v))

// ---------------------------------------------------------------------------
// Tiled SGEMM with bias: C[M,N] = A[M,K] @ B[K,N] + bias[N]
// BM=128, BN=128, BK=8, 256 threads, 8x8 per-thread microtile, FFMA2 inner loop.
// ---------------------------------------------------------------------------
template <int BM, int BN, int BK, int TM, int TN>
__global__ __launch_bounds__(256) void sgemm_bias_kernel(
    const float* __restrict__ A, const float* __restrict__ B,
    const float* __restrict__ bias, float* __restrict__ C,
    int M, int N, int K)
{
    __shared__ float As[BK][BM + 4];   // 528B rows: 16B-aligned, conflict-free
    __shared__ float Bs[BK][BN];

    const int tid = threadIdx.x;
    const int tx = tid % (BN / TN);    // 0..15
    const int ty = tid / (BN / TN);    // 0..15
    const int m0 = blockIdx.y * BM;
    const int n0 = blockIdx.x * BN;

    // packed accumulators: acc2[i][jp] holds columns (2jp, 2jp+1) for row i
    unsigned long long acc2[TM][TN / 2];
#pragma unroll
    for (int i = 0; i < TM; i++)
#pragma unroll
        for (int j = 0; j < TN / 2; j++) acc2[i][j] = 0ULL;

    for (int k0 = 0; k0 < K; k0 += BK) {
#pragma unroll
        for (int i = 0; i < (BM * BK) / 256; i++) {
            int idx = tid + i * 256;
            int r = idx / BK, c = idx % BK;
            As[c][r] = A[(size_t)(m0 + r) * K + k0 + c];
        }
#pragma unroll
        for (int i = 0; i < (BK * BN) / 256; i++) {
            int idx = tid + i * 256;
            int r = idx / BN, c = idx % BN;
            Bs[r][c] = B[(size_t)(k0 + r) * N + n0 + c];
        }
        __syncthreads();

#pragma unroll
        for (int k = 0; k < BK; k++) {
            // A fragment: load 8 floats, duplicate each into a packed pair
            unsigned long long ra2[TM];
            const float4* ap = (const float4*)&As[k][ty * TM];
#pragma unroll
            for (int v = 0; v < TM / 4; v++) {
                float4 t = ap[v];
                PACK2(ra2[v * 4 + 0], t.x, t.x);
                PACK2(ra2[v * 4 + 1], t.y, t.y);
                PACK2(ra2[v * 4 + 2], t.z, t.z);
                PACK2(ra2[v * 4 + 3], t.w, t.w);
            }
            // B fragment: adjacent column pairs are already packed in smem
            unsigned long long rb2[TN / 2];
            const ulonglong2* bp = (const ulonglong2*)&Bs[k][tx * TN];
#pragma unroll
            for (int v = 0; v < TN / 4; v++) {
                ulonglong2 t = bp[v];
                rb2[v * 2 + 0] = t.x;
                rb2[v * 2 + 1] = t.y;
            }
#pragma unroll
            for (int i = 0; i < TM; i++)
#pragma unroll
                for (int j = 0; j < TN / 2; j++)
                    FMA2(acc2[i][j], ra2[i], rb2[j]);
        }
        __syncthreads();
    }

    // epilogue: unpack, add bias, vectorized stores
#pragma unroll
    for (int i = 0; i < TM; i++) {
        int m = m0 + ty * TM + i;
#pragma unroll
        for (int v = 0; v < TN / 4; v++) {
            int n = n0 + tx * TN + v * 4;
            float4 bv = *(const float4*)&bias[n];
            float e0, e1, e2, e3;
            UNPACK2(e0, e1, acc2[i][v * 2 + 0]);
            UNPACK2(e2, e3, acc2[i][v * 2 + 1]);
            float4 r;
            r.x = e0 + bv.x; r.y = e1 + bv.y; r.z = e2 + bv.z; r.w = e3 + bv.w;
            *(float4*)&C[(size_t)m * N + n] = r;
        }
    }
}

// ---------------------------------------------------------------------------
// Flash attention (fp32, online softmax), FFMA2 inner loops.
// Grid: (SEQ/128, NH, BATCH), 128 threads; thread t owns query row.
// ---------------------------------------------------------------------------
__global__ __launch_bounds__(128) void flash_attn_kernel(
    const float* __restrict__ qkv, float* __restrict__ att)
{
    constexpr int BM = 128;
    constexpr int BN = 64;

    __shared__ float Ks[BN][HD];
    __shared__ float Vs[BN][HD];

    const int tid = threadIdx.x;
    const int qt = blockIdx.x;
    const int h  = blockIdx.y;
    const int b  = blockIdx.z;
    const int qrow = qt * BM + tid;

    // q row, scaled, packed into 32 f32x2 pairs
    const float* qptr = qkv + (size_t)(b * SEQ + qrow) * QKV_N + h * HD;
    unsigned long long q2[HD / 2];
#pragma unroll
    for (int v = 0; v < HD / 4; v++) {
        float4 t = ((const float4*)qptr)[v];
        PACK2(q2[v * 2 + 0], t.x * 0.125f, t.y * 0.125f);
        PACK2(q2[v * 2 + 1], t.z * 0.125f, t.w * 0.125f);
    }

    unsigned long long o2[HD / 2];
#pragma unroll
    for (int v = 0; v < HD / 2; v++) o2[v] = 0ULL;
    float m = -1e30f, l = 0.f;

    const int ktiles = (qt * BM + BM - 1) / BN + 1;

    for (int kt = 0; kt < ktiles; kt++) {
        const float* kbase = qkv + (size_t)(b * SEQ + kt * BN) * QKV_N + CH + h * HD;
        const float* vbase = kbase + CH;

        __syncthreads();
#pragma unroll
        for (int i = 0; i < 8; i++) {
            int idx = tid + i * 128;
            int r = idx >> 4;
            int c4 = idx & 15;
            ((float4*)&Ks[r][0])[c4] = ((const float4*)(kbase + (size_t)r * QKV_N))[c4];
            ((float4*)&Vs[r][0])[c4] = ((const float4*)(vbase + (size_t)r * QKV_N))[c4];
        }
        __syncthreads();

        int nch = 0;
        if (qrow >= kt * BN) {
            int last = qrow - kt * BN;
            nch = min(8, (last >> 3) + 1);
        }

        for (int jj = 0; jj < nch; jj++) {
            const int kfirst = kt * BN + jj * 8;

            float s[8];
#pragma unroll
            for (int j = 0; j < 8; j++) {
                const ulonglong2* kr = (const ulonglong2*)&Ks[jj * 8 + j][0];
                unsigned long long a0 = 0ULL, a1 = 0ULL;
#pragma unroll
                for (int p = 0; p < 16; p++) {
                    ulonglong2 kv = kr[p];
                    FMA2(a0, q2[p * 2 + 0], kv.x);
                    FMA2(a1, q2[p * 2 + 1], kv.y);
                }
                float e0, e1, e2, e3;
                UNPACK2(e0, e1, a0);
                UNPACK2(e2, e3, a1);
                s[j] = (e0 + e2) + (e1 + e3);
            }

#pragma unroll
            for (int j = 0; j < 8; j++)
                if (kfirst + j > qrow) s[j] = -1e30f;

            float mc = s[0];
#pragma unroll
            for (int j = 1; j < 8; j++) mc = fmaxf(mc, s[j]);
            float m_new = fmaxf(m, mc);
            float corr = __expf(m - m_new);
            float p[8], psum = 0.f;
#pragma unroll
            for (int j = 0; j < 8; j++) {
                p[j] = __expf(s[j] - m_new);
                psum += p[j];
            }
            l = l * corr + psum;
            m = m_new;

            unsigned long long cc;
            PACK2(cc, corr, corr);
#pragma unroll
            for (int v = 0; v < HD / 2; v++) MUL2(o2[v], o2[v], cc);

#pragma unroll
            for (int j = 0; j < 8; j++) {
                const ulonglong2* vr = (const ulonglong2*)&Vs[jj * 8 + j][0];
                unsigned long long pp;
                PACK2(pp, p[j], p[j]);
#pragma unroll
                for (int v = 0; v < 16; v++) {
                    ulonglong2 vv = vr[v];
                    FMA2(o2[v * 2 + 0], pp, vv.x);
                    FMA2(o2[v * 2 + 1], pp, vv.y);
                }
            }
        }
    }

    const float inv_l = 1.f / l;
    float* optr = att + (size_t)(b * SEQ + qrow) * CH + h * HD;
#pragma unroll
    for (int v = 0; v < HD / 4; v++) {
        float e0, e1, e2, e3;
        UNPACK2(e0, e1, o2[v * 2 + 0]);
        UNPACK2(e2, e3, o2[v * 2 + 1]);
        float4 r;
        r.x = e0 * inv_l; r.y = e1 * inv_l; r.z = e2 * inv_l; r.w = e3 * inv_l;
        ((float4*)optr)[v] = r;
    }
}

// ---------------------------------------------------------------------------
extern "C" void kernel_launch(void* const* d_in, const int* in_sizes, int n_in,
                              void* d_out, int out_size)
{
    const float* x      = (const float*)d_in[0];
    const float* w_attn = (const float*)d_in[1];
    const float* b_attn = (const float*)d_in[2];
    const float* w_proj = (const float*)d_in[3];
    const float* b_proj = (const float*)d_in[4];
    float* out = (float*)d_out;

    float* qkv = nullptr;
    float* att = nullptr;
    cudaGetSymbolAddress((void**)&qkv, g_qkv);
    cudaGetSymbolAddress((void**)&att, g_att);

    {
        dim3 grid(QKV_N / 128, M_ROWS / 128);
        sgemm_bias_kernel<128, 128, 8, 8, 8><<<grid, 256>>>(
            x, w_attn, b_attn, qkv, M_ROWS, QKV_N, CH);
    }
    {
        dim3 grid(SEQ / 128, NH, BATCH);
        flash_attn_kernel<<<grid, 128>>>(qkv, att);
    }
    {
        dim3 grid(CH / 128, M_ROWS / 128);
        sgemm_bias_kernel<128, 128, 8, 8, 8><<<grid, 256>>>(
            att, w_proj, b_proj, out, M_ROWS, CH, CH);
    }
}

// round 12
// speedup vs baseline: 2.2791x; 1.3546x over previous
#include <cuda_runtime.h>
#include <cuda_bf16.h>
#include <cstdint>

// GPT-2 small attention: x[1,8,1024,768], w_attn[768,2304], w_proj[768,768]
#define BATCH 8
#define SEQ   1024
#define CH    768
#define NH    12
#define HD    64
#define M_ROWS (BATCH * SEQ)      // 8192
#define QKV_N (3 * CH)            // 2304

// ---------------- scratch (__device__ globals; no allocs allowed) ----------
__device__ float g_qkv[M_ROWS * QKV_N];
__device__ float g_att[M_ROWS * CH];
__device__ __nv_bfloat16 g_xhi[M_ROWS * CH];
__device__ __nv_bfloat16 g_xlo[M_ROWS * CH];
__device__ __nv_bfloat16 g_ahi[M_ROWS * CH];
__device__ __nv_bfloat16 g_alo[M_ROWS * CH];
__device__ __nv_bfloat16 g_wathi[QKV_N * CH];   // w_attn^T [2304,768]
__device__ __nv_bfloat16 g_watlo[QKV_N * CH];
__device__ __nv_bfloat16 g_wphi[CH * CH];       // w_proj^T [768,768]
__device__ __nv_bfloat16 g_wplo[CH * CH];

// ---------------------------------------------------------------------------
// Prep kernels: fp32 -> bf16 hi/lo split (and transposed variant for weights)
// ---------------------------------------------------------------------------
__global__ void split_kernel(const float* __restrict__ src,
                             __nv_bfloat16* __restrict__ hi, __nv_bfloat16* __restrict__ lo, int n) {
    int i = (blockIdx.x * 256 + threadIdx.x) * 4;
    if (i >= n) return;
    float4 v = *(const float4*)(src + i);
    __nv_bfloat16 h0 = __float2bfloat16_rn(v.x), h1 = __float2bfloat16_rn(v.y);
    __nv_bfloat16 h2 = __float2bfloat16_rn(v.z), h3 = __float2bfloat16_rn(v.w);
    hi[i + 0] = h0; hi[i + 1] = h1; hi[i + 2] = h2; hi[i + 3] = h3;
    lo[i + 0] = __float2bfloat16_rn(v.x - __bfloat162float(h0));
    lo[i + 1] = __float2bfloat16_rn(v.y - __bfloat162float(h1));
    lo[i + 2] = __float2bfloat16_rn(v.z - __bfloat162float(h2));
    lo[i + 3] = __float2bfloat16_rn(v.w - __bfloat162float(h3));
}

// w[K,N] -> wT hi/lo [N,K]
__global__ void transpose_split_kernel(const float* __restrict__ w,
                                       __nv_bfloat16* __restrict__ thi, __nv_bfloat16* __restrict__ tlo,
                                       int K, int N) {
    int idx = blockIdx.x * 256 + threadIdx.x;    // idx = n*K + k
    if (idx >= K * N) return;
    int n = idx / K, k = idx % K;
    float v = w[(size_t)k * N + n];
    __nv_bfloat16 h = __float2bfloat16_rn(v);
    thi[idx] = h;
    tlo[idx] = __float2bfloat16_rn(v - __bfloat162float(h));
}

// ---------------------------------------------------------------------------
// HMMA GEMM: C[M,N] = Ahi@Bhi^T + Ahi@Blo^T + Alo@Bhi^T + bias
// A* : [M,K] bf16 row-major; B* : [N,K] bf16 row-major (= col-major KxN for mma)
// CTA tile 128x128, 8 warps (2x4), warp tile 64x32 (4x4 m16n8k16 tiles).
// Smem chunks [128][32] bf16 with row stride 40 halves (conflict-free frags).
// ---------------------------------------------------------------------------
#define KCHUNK 32
#define ROWP   40                               // padded row stride (halves)
#define ARR_B  (128 * ROWP * 2)                 // 10240 bytes per array chunk
#define BUFH_B (4 * ARR_B)                      // Ahi, Alo, Bhi, Blo = 40960
#define GEMM_SMEM_H (2 * BUFH_B)                // double buffered = 81920

#define MMA_BF16(c, a, b)                                                      \
    asm volatile("mma.sync.aligned.m16n8k16.row.col.f32.bf16.bf16.f32 "        \
                 "{%0,%1,%2,%3}, {%4,%5,%6,%7}, {%8,%9}, {%0,%1,%2,%3};"       \
                 : "+f"((c)[0]), "+f"((c)[1]), "+f"((c)[2]), "+f"((c)[3])      \
                 : "r"((a)[0]), "r"((a)[1]), "r"((a)[2]), "r"((a)[3]),         \
                   "r"((b)[0]), "r"((b)[1]))

__global__ __launch_bounds__(256, 1) void hmma_gemm_kernel(
    const __nv_bfloat16* __restrict__ Ahi, const __nv_bfloat16* __restrict__ Alo,
    const __nv_bfloat16* __restrict__ Bhi, const __nv_bfloat16* __restrict__ Blo,
    const float* __restrict__ bias, float* __restrict__ C, int M, int N, int K)
{
    extern __shared__ char smem[];
    const int tid  = threadIdx.x;
    const int lane = tid & 31;
    const int wid  = tid >> 5;
    const int wm   = wid >> 2;          // 0..1 (M dimension)
    const int wn   = wid & 3;           // 0..3 (N dimension)
    const int gid  = lane >> 2;         // 0..7
    const int tig  = lane & 3;          // 0..3
    const int m0 = blockIdx.y * 128;
    const int n0 = blockIdx.x * 128;
    const int nch = K / KCHUNK;

    float acc[4][4][4];
#pragma unroll
    for (int i = 0; i < 4; i++)
#pragma unroll
        for (int j = 0; j < 4; j++)
#pragma unroll
            for (int v = 0; v < 4; v++) acc[i][j][v] = 0.f;

    const __nv_bfloat16* srcs[4] = { Ahi + (size_t)m0 * K, Alo + (size_t)m0 * K,
                                     Bhi + (size_t)n0 * K, Blo + (size_t)n0 * K };
    uint4 st[4][2];

    // ---- load chunk kc into staging regs ----
#define LOAD_CHUNK(kc) do {                                                    \
    _Pragma("unroll")                                                          \
    for (int t = 0; t < 4; t++) {                                              \
        _Pragma("unroll")                                                      \
        for (int i = 0; i < 2; i++) {                                          \
            int v = tid * 2 + i;                                               \
            int r = v >> 2, cv = v & 3;                                        \
            st[t][i] = *(const uint4*)(srcs[t] + (size_t)r * K + (kc) * KCHUNK + cv * 8); \
        }                                                                      \
    }                                                                          \
} while (0)

    // ---- store staging regs into smem buffer p ----
#define STORE_CHUNK(p) do {                                                    \
    _Pragma("unroll")                                                          \
    for (int t = 0; t < 4; t++) {                                              \
        _Pragma("unroll")                                                      \
        for (int i = 0; i < 2; i++) {                                          \
            int v = tid * 2 + i;                                               \
            int r = v >> 2, cv = v & 3;                                        \
            *(uint4*)(smem + (p) * BUFH_B + t * ARR_B + r * (ROWP * 2) + cv * 16) = st[t][i]; \
        }                                                                      \
    }                                                                          \
} while (0)

    LOAD_CHUNK(0);
    STORE_CHUNK(0);
    __syncthreads();

    for (int kc = 0; kc < nch; kc++) {
        const int p = kc & 1;
        if (kc + 1 < nch) LOAD_CHUNK(kc + 1);

        const __nv_bfloat16* Ah = (const __nv_bfloat16*)(smem + p * BUFH_B);
        const __nv_bfloat16* Al = (const __nv_bfloat16*)(smem + p * BUFH_B + ARR_B);
        const __nv_bfloat16* Bh = (const __nv_bfloat16*)(smem + p * BUFH_B + 2 * ARR_B);
        const __nv_bfloat16* Bl = (const __nv_bfloat16*)(smem + p * BUFH_B + 3 * ARR_B);

#pragma unroll
        for (int ks = 0; ks < 2; ks++) {
            const int c = ks * 16 + 2 * tig;
            uint32_t ah[4][4], al[4][4];
#pragma unroll
            for (int tm = 0; tm < 4; tm++) {
                int r = wm * 64 + tm * 16 + gid;
                ah[tm][0] = *(const uint32_t*)(Ah + r * ROWP + c);
                ah[tm][1] = *(const uint32_t*)(Ah + (r + 8) * ROWP + c);
                ah[tm][2] = *(const uint32_t*)(Ah + r * ROWP + c + 8);
                ah[tm][3] = *(const uint32_t*)(Ah + (r + 8) * ROWP + c + 8);
                al[tm][0] = *(const uint32_t*)(Al + r * ROWP + c);
                al[tm][1] = *(const uint32_t*)(Al + (r + 8) * ROWP + c);
                al[tm][2] = *(const uint32_t*)(Al + r * ROWP + c + 8);
                al[tm][3] = *(const uint32_t*)(Al + (r + 8) * ROWP + c + 8);
            }
            uint32_t bh[4][2], bl[4][2];
#pragma unroll
            for (int tn = 0; tn < 4; tn++) {
                int nr = wn * 32 + tn * 8 + gid;
                bh[tn][0] = *(const uint32_t*)(Bh + nr * ROWP + c);
                bh[tn][1] = *(const uint32_t*)(Bh + nr * ROWP + c + 8);
                bl[tn][0] = *(const uint32_t*)(Bl + nr * ROWP + c);
                bl[tn][1] = *(const uint32_t*)(Bl + nr * ROWP + c + 8);
            }
#pragma unroll
            for (int tm = 0; tm < 4; tm++)
#pragma unroll
                for (int tn = 0; tn < 4; tn++) {
                    MMA_BF16(acc[tm][tn], ah[tm], bh[tn]);
                    MMA_BF16(acc[tm][tn], ah[tm], bl[tn]);
                    MMA_BF16(acc[tm][tn], al[tm], bh[tn]);
                }
        }

        if (kc + 1 < nch) STORE_CHUNK((kc + 1) & 1);
        __syncthreads();
    }

    // ---- epilogue: bias + store (float2 per row/tile) ----
#pragma unroll
    for (int tm = 0; tm < 4; tm++) {
        int r = m0 + wm * 64 + tm * 16 + gid;
#pragma unroll
        for (int tn = 0; tn < 4; tn++) {
            int n = n0 + wn * 32 + tn * 8 + 2 * tig;
            float2 bv = *(const float2*)(bias + n);
            float2 lo, hi2;
            lo.x = acc[tm][tn][0] + bv.x;
            lo.y = acc[tm][tn][1] + bv.y;
            hi2.x = acc[tm][tn][2] + bv.x;
            hi2.y = acc[tm][tn][3] + bv.y;
            *(float2*)(C + (size_t)r * N + n) = lo;
            *(float2*)(C + (size_t)(r + 8) * N + n) = hi2;
        }
    }
}

// ---------------------------------------------------------------------------
// Flash attention (fp32, online softmax), FFMA2 inner loops. (unchanged, verified)
// ---------------------------------------------------------------------------
#define FMA2(d, a, b) asm("fma.rn.f32x2 %0, %1, %2, %0;" : "+l"(d) : "l"(a), "l"(b))
#define MUL2(d, a, b) asm("mul.rn.f32x2 %0, %1, %2;" : "=l"(d) : "l"(a), "l"(b))
#define PACK2(d, lo, hi) asm("mov.b64 %0, {%1, %2};" : "=l"(d) : "f"(lo), "f"(hi))
#define UNPACK2(lo, hi, v) asm("mov.b64 {%0, %1}, %2;" : "=f"(lo), "=f"(hi) : "l"(v))

__global__ __launch_bounds__(128) void flash_attn_kernel(
    const float* __restrict__ qkv, float* __restrict__ att)
{
    constexpr int BM = 128;
    constexpr int BN = 64;

    __shared__ float Ks[BN][HD];
    __shared__ float Vs[BN][HD];

    const int tid = threadIdx.x;
    const int qt = blockIdx.x;
    const int h  = blockIdx.y;
    const int b  = blockIdx.z;
    const int qrow = qt * BM + tid;

    const float* qptr = qkv + (size_t)(b * SEQ + qrow) * QKV_N + h * HD;
    unsigned long long q2[HD / 2];
#pragma unroll
    for (int v = 0; v < HD / 4; v++) {
        float4 t = ((const float4*)qptr)[v];
        PACK2(q2[v * 2 + 0], t.x * 0.125f, t.y * 0.125f);
        PACK2(q2[v * 2 + 1], t.z * 0.125f, t.w * 0.125f);
    }

    unsigned long long o2[HD / 2];
#pragma unroll
    for (int v = 0; v < HD / 2; v++) o2[v] = 0ULL;
    float m = -1e30f, l = 0.f;

    const int ktiles = (qt * BM + BM - 1) / BN + 1;

    for (int kt = 0; kt < ktiles; kt++) {
        const float* kbase = qkv + (size_t)(b * SEQ + kt * BN) * QKV_N + CH + h * HD;
        const float* vbase = kbase + CH;

        __syncthreads();
#pragma unroll
        for (int i = 0; i < 8; i++) {
            int idx = tid + i * 128;
            int r = idx >> 4;
            int c4 = idx & 15;
            ((float4*)&Ks[r][0])[c4] = ((const float4*)(kbase + (size_t)r * QKV_N))[c4];
            ((float4*)&Vs[r][0])[c4] = ((const float4*)(vbase + (size_t)r * QKV_N))[c4];
        }
        __syncthreads();

        int nch = 0;
        if (qrow >= kt * BN) {
            int last = qrow - kt * BN;
            nch = min(8, (last >> 3) + 1);
        }

        for (int jj = 0; jj < nch; jj++) {
            const int kfirst = kt * BN + jj * 8;

            float s[8];
#pragma unroll
            for (int j = 0; j < 8; j++) {
                const ulonglong2* kr = (const ulonglong2*)&Ks[jj * 8 + j][0];
                unsigned long long a0 = 0ULL, a1 = 0ULL;
#pragma unroll
                for (int p = 0; p < 16; p++) {
                    ulonglong2 kv = kr[p];
                    FMA2(a0, q2[p * 2 + 0], kv.x);
                    FMA2(a1, q2[p * 2 + 1], kv.y);
                }
                float e0, e1, e2, e3;
                UNPACK2(e0, e1, a0);
                UNPACK2(e2, e3, a1);
                s[j] = (e0 + e2) + (e1 + e3);
            }

#pragma unroll
            for (int j = 0; j < 8; j++)
                if (kfirst + j > qrow) s[j] = -1e30f;

            float mc = s[0];
#pragma unroll
            for (int j = 1; j < 8; j++) mc = fmaxf(mc, s[j]);
            float m_new = fmaxf(m, mc);
            float corr = __expf(m - m_new);
            float p[8], psum = 0.f;
#pragma unroll
            for (int j = 0; j < 8; j++) {
                p[j] = __expf(s[j] - m_new);
                psum += p[j];
            }
            l = l * corr + psum;
            m = m_new;

            unsigned long long cc;
            PACK2(cc, corr, corr);
#pragma unroll
            for (int v = 0; v < HD / 2; v++) MUL2(o2[v], o2[v], cc);

#pragma unroll
            for (int j = 0; j < 8; j++) {
                const ulonglong2* vr = (const ulonglong2*)&Vs[jj * 8 + j][0];
                unsigned long long pp;
                PACK2(pp, p[j], p[j]);
#pragma unroll
                for (int v = 0; v < 16; v++) {
                    ulonglong2 vv = vr[v];
                    FMA2(o2[v * 2 + 0], pp, vv.x);
                    FMA2(o2[v * 2 + 1], pp, vv.y);
                }
            }
        }
    }

    const float inv_l = 1.f / l;
    float* optr = att + (size_t)(b * SEQ + qrow) * CH + h * HD;
#pragma unroll
    for (int v = 0; v < HD / 4; v++) {
        float e0, e1, e2, e3;
        UNPACK2(e0, e1, o2[v * 2 + 0]);
        UNPACK2(e2, e3, o2[v * 2 + 1]);
        float4 r;
        r.x = e0 * inv_l; r.y = e1 * inv_l; r.z = e2 * inv_l; r.w = e3 * inv_l;
        ((float4*)optr)[v] = r;
    }
}

// ---------------------------------------------------------------------------
extern "C" void kernel_launch(void* const* d_in, const int* in_sizes, int n_in,
                              void* d_out, int out_size)
{
    const float* x      = (const float*)d_in[0];
    const float* w_attn = (const float*)d_in[1];
    const float* b_attn = (const float*)d_in[2];
    const float* w_proj = (const float*)d_in[3];
    const float* b_proj = (const float*)d_in[4];
    float* out = (float*)d_out;

    float *qkv, *att;
    __nv_bfloat16 *xhi, *xlo, *ahi, *alo, *wathi, *watlo, *wphi, *wplo;
    cudaGetSymbolAddress((void**)&qkv, g_qkv);
    cudaGetSymbolAddress((void**)&att, g_att);
    cudaGetSymbolAddress((void**)&xhi, g_xhi);
    cudaGetSymbolAddress((void**)&xlo, g_xlo);
    cudaGetSymbolAddress((void**)&ahi, g_ahi);
    cudaGetSymbolAddress((void**)&alo, g_alo);
    cudaGetSymbolAddress((void**)&wathi, g_wathi);
    cudaGetSymbolAddress((void**)&watlo, g_watlo);
    cudaGetSymbolAddress((void**)&wphi, g_wphi);
    cudaGetSymbolAddress((void**)&wplo, g_wplo);

    cudaFuncSetAttribute(hmma_gemm_kernel, cudaFuncAttributeMaxDynamicSharedMemorySize, GEMM_SMEM_H);

    // prep: split x; transpose+split weights
    split_kernel<<<(M_ROWS * CH) / 1024, 256>>>(x, xhi, xlo, M_ROWS * CH);
    transpose_split_kernel<<<(CH * QKV_N + 255) / 256, 256>>>(w_attn, wathi, watlo, CH, QKV_N);
    transpose_split_kernel<<<(CH * CH + 255) / 256, 256>>>(w_proj, wphi, wplo, CH, CH);

    // 1) QKV GEMM (HMMA): [8192,768] @ [768,2304]
    {
        dim3 grid(QKV_N / 128, M_ROWS / 128);
        hmma_gemm_kernel<<<grid, 256, GEMM_SMEM_H>>>(xhi, xlo, wathi, watlo, b_attn, qkv,
                                                     M_ROWS, QKV_N, CH);
    }

    // 2) Flash attention
    {
        dim3 grid(SEQ / 128, NH, BATCH);
        flash_attn_kernel<<<grid, 128>>>(qkv, att);
    }

    // 3) split att, then proj GEMM (HMMA): [8192,768] @ [768,768]
    split_kernel<<<(M_ROWS * CH) / 1024, 256>>>(att, ahi, alo, M_ROWS * CH);
    {
        dim3 grid(CH / 128, M_ROWS / 128);
        hmma_gemm_kernel<<<grid, 256, GEMM_SMEM_H>>>(ahi, alo, wphi, wplo, b_proj, out,
                                                     M_ROWS, CH, CH);
    }
}

// round 15
// speedup vs baseline: 4.5495x; 1.9962x over previous
#include <cuda_runtime.h>
#include <cuda_bf16.h>
#include <cstdint>

// GPT-2 small attention: x[1,8,1024,768], w_attn[768,2304], w_proj[768,768]
#define BATCH 8
#define SEQ   1024
#define CH    768
#define NH    12
#define HD    64
#define M_ROWS (BATCH * SEQ)      // 8192
#define QKV_N (3 * CH)            // 2304

// ---------------- scratch (__device__ globals; no allocs allowed) ----------
__device__ float g_qkv[M_ROWS * QKV_N];
__device__ float g_att[M_ROWS * CH];
__device__ __nv_bfloat16 g_xhi[M_ROWS * CH];
__device__ __nv_bfloat16 g_xlo[M_ROWS * CH];
__device__ __nv_bfloat16 g_ahi[M_ROWS * CH];
__device__ __nv_bfloat16 g_alo[M_ROWS * CH];
__device__ __nv_bfloat16 g_wathi[QKV_N * CH];   // w_attn^T [2304,768]
__device__ __nv_bfloat16 g_watlo[QKV_N * CH];
__device__ __nv_bfloat16 g_wphi[CH * CH];       // w_proj^T [768,768]
__device__ __nv_bfloat16 g_wplo[CH * CH];

// ---------------------------------------------------------------------------
// Prep kernels: fp32 -> bf16 hi/lo split (and transposed variant for weights)
// ---------------------------------------------------------------------------
__global__ void split_kernel(const float* __restrict__ src,
                             __nv_bfloat16* __restrict__ hi, __nv_bfloat16* __restrict__ lo, int n) {
    int i = (blockIdx.x * 256 + threadIdx.x) * 4;
    if (i >= n) return;
    float4 v = *(const float4*)(src + i);
    __nv_bfloat16 h0 = __float2bfloat16_rn(v.x), h1 = __float2bfloat16_rn(v.y);
    __nv_bfloat16 h2 = __float2bfloat16_rn(v.z), h3 = __float2bfloat16_rn(v.w);
    hi[i + 0] = h0; hi[i + 1] = h1; hi[i + 2] = h2; hi[i + 3] = h3;
    lo[i + 0] = __float2bfloat16_rn(v.x - __bfloat162float(h0));
    lo[i + 1] = __float2bfloat16_rn(v.y - __bfloat162float(h1));
    lo[i + 2] = __float2bfloat16_rn(v.z - __bfloat162float(h2));
    lo[i + 3] = __float2bfloat16_rn(v.w - __bfloat162float(h3));
}

// w[K,N] -> wT hi/lo [N,K]
__global__ void transpose_split_kernel(const float* __restrict__ w,
                                       __nv_bfloat16* __restrict__ thi, __nv_bfloat16* __restrict__ tlo,
                                       int K, int N) {
    int idx = blockIdx.x * 256 + threadIdx.x;    // idx = n*K + k
    if (idx >= K * N) return;
    int n = idx / K, k = idx % K;
    float v = w[(size_t)k * N + n];
    __nv_bfloat16 h = __float2bfloat16_rn(v);
    thi[idx] = h;
    tlo[idx] = __float2bfloat16_rn(v - __bfloat162float(h));
}

// ---------------------------------------------------------------------------
// HMMA GEMM (UNCHANGED — hardware-verified in R12)
// ---------------------------------------------------------------------------
#define KCHUNK 32
#define ROWP   40                               // padded row stride (halves)
#define ARR_B  (128 * ROWP * 2)                 // 10240 bytes per array chunk
#define BUFH_B (4 * ARR_B)                      // Ahi, Alo, Bhi, Blo = 40960
#define GEMM_SMEM_H (2 * BUFH_B)                // double buffered = 81920

#define MMA_BF16(c, a, b)                                                      \
    asm volatile("mma.sync.aligned.m16n8k16.row.col.f32.bf16.bf16.f32 "        \
                 "{%0,%1,%2,%3}, {%4,%5,%6,%7}, {%8,%9}, {%0,%1,%2,%3};"       \
                 : "+f"((c)[0]), "+f"((c)[1]), "+f"((c)[2]), "+f"((c)[3])      \
                 : "r"((a)[0]), "r"((a)[1]), "r"((a)[2]), "r"((a)[3]),         \
                   "r"((b)[0]), "r"((b)[1]))

__global__ __launch_bounds__(256, 1) void hmma_gemm_kernel(
    const __nv_bfloat16* __restrict__ Ahi, const __nv_bfloat16* __restrict__ Alo,
    const __nv_bfloat16* __restrict__ Bhi, const __nv_bfloat16* __restrict__ Blo,
    const float* __restrict__ bias, float* __restrict__ C, int M, int N, int K)
{
    extern __shared__ char smem[];
    const int tid  = threadIdx.x;
    const int lane = tid & 31;
    const int wid  = tid >> 5;
    const int wm   = wid >> 2;          // 0..1 (M dimension)
    const int wn   = wid & 3;           // 0..3 (N dimension)
    const int gid  = lane >> 2;         // 0..7
    const int tig  = lane & 3;          // 0..3
    const int m0 = blockIdx.y * 128;
    const int n0 = blockIdx.x * 128;
    const int nch = K / KCHUNK;

    float acc[4][4][4];
#pragma unroll
    for (int i = 0; i < 4; i++)
#pragma unroll
        for (int j = 0; j < 4; j++)
#pragma unroll
            for (int v = 0; v < 4; v++) acc[i][j][v] = 0.f;

    const __nv_bfloat16* srcs[4] = { Ahi + (size_t)m0 * K, Alo + (size_t)m0 * K,
                                     Bhi + (size_t)n0 * K, Blo + (size_t)n0 * K };
    uint4 st[4][2];

#define LOAD_CHUNK(kc) do {                                                    \
    _Pragma("unroll")                                                          \
    for (int t = 0; t < 4; t++) {                                              \
        _Pragma("unroll")                                                      \
        for (int i = 0; i < 2; i++) {                                          \
            int v = tid * 2 + i;                                               \
            int r = v >> 2, cv = v & 3;                                        \
            st[t][i] = *(const uint4*)(srcs[t] + (size_t)r * K + (kc) * KCHUNK + cv * 8); \
        }                                                                      \
    }                                                                          \
} while (0)

#define STORE_CHUNK(p) do {                                                    \
    _Pragma("unroll")                                                          \
    for (int t = 0; t < 4; t++) {                                              \
        _Pragma("unroll")                                                      \
        for (int i = 0; i < 2; i++) {                                          \
            int v = tid * 2 + i;                                               \
            int r = v >> 2, cv = v & 3;                                        \
            *(uint4*)(smem + (p) * BUFH_B + t * ARR_B + r * (ROWP * 2) + cv * 16) = st[t][i]; \
        }                                                                      \
    }                                                                          \
} while (0)

    LOAD_CHUNK(0);
    STORE_CHUNK(0);
    __syncthreads();

    for (int kc = 0; kc < nch; kc++) {
        const int p = kc & 1;
        if (kc + 1 < nch) LOAD_CHUNK(kc + 1);

        const __nv_bfloat16* Ah = (const __nv_bfloat16*)(smem + p * BUFH_B);
        const __nv_bfloat16* Al = (const __nv_bfloat16*)(smem + p * BUFH_B + ARR_B);
        const __nv_bfloat16* Bh = (const __nv_bfloat16*)(smem + p * BUFH_B + 2 * ARR_B);
        const __nv_bfloat16* Bl = (const __nv_bfloat16*)(smem + p * BUFH_B + 3 * ARR_B);

#pragma unroll
        for (int ks = 0; ks < 2; ks++) {
            const int c = ks * 16 + 2 * tig;
            uint32_t ah[4][4], al[4][4];
#pragma unroll
            for (int tm = 0; tm < 4; tm++) {
                int r = wm * 64 + tm * 16 + gid;
                ah[tm][0] = *(const uint32_t*)(Ah + r * ROWP + c);
                ah[tm][1] = *(const uint32_t*)(Ah + (r + 8) * ROWP + c);
                ah[tm][2] = *(const uint32_t*)(Ah + r * ROWP + c + 8);
                ah[tm][3] = *(const uint32_t*)(Ah + (r + 8) * ROWP + c + 8);
                al[tm][0] = *(const uint32_t*)(Al + r * ROWP + c);
                al[tm][1] = *(const uint32_t*)(Al + (r + 8) * ROWP + c);
                al[tm][2] = *(const uint32_t*)(Al + r * ROWP + c + 8);
                al[tm][3] = *(const uint32_t*)(Al + (r + 8) * ROWP + c + 8);
            }
            uint32_t bh[4][2], bl[4][2];
#pragma unroll
            for (int tn = 0; tn < 4; tn++) {
                int nr = wn * 32 + tn * 8 + gid;
                bh[tn][0] = *(const uint32_t*)(Bh + nr * ROWP + c);
                bh[tn][1] = *(const uint32_t*)(Bh + nr * ROWP + c + 8);
                bl[tn][0] = *(const uint32_t*)(Bl + nr * ROWP + c);
                bl[tn][1] = *(const uint32_t*)(Bl + nr * ROWP + c + 8);
            }
#pragma unroll
            for (int tm = 0; tm < 4; tm++)
#pragma unroll
                for (int tn = 0; tn < 4; tn++) {
                    MMA_BF16(acc[tm][tn], ah[tm], bh[tn]);
                    MMA_BF16(acc[tm][tn], ah[tm], bl[tn]);
                    MMA_BF16(acc[tm][tn], al[tm], bh[tn]);
                }
        }

        if (kc + 1 < nch) STORE_CHUNK((kc + 1) & 1);
        __syncthreads();
    }

#pragma unroll
    for (int tm = 0; tm < 4; tm++) {
        int r = m0 + wm * 64 + tm * 16 + gid;
#pragma unroll
        for (int tn = 0; tn < 4; tn++) {
            int n = n0 + wn * 32 + tn * 8 + 2 * tig;
            float2 bv = *(const float2*)(bias + n);
            float2 lo, hi2;
            lo.x = acc[tm][tn][0] + bv.x;
            lo.y = acc[tm][tn][1] + bv.y;
            hi2.x = acc[tm][tn][2] + bv.x;
            hi2.y = acc[tm][tn][3] + bv.y;
            *(float2*)(C + (size_t)r * N + n) = lo;
            *(float2*)(C + (size_t)(r + 8) * N + n) = hi2;
        }
    }
}

// ---------------------------------------------------------------------------
// Flash attention on HMMA.
// Grid (SEQ/128, NH, BATCH), 256 threads = 8 warps; warp owns 16 q-rows.
// S = Q@K^T in bf16 (softmax absorbs tiny abs score error);
// P@V in hi/lo 3-product (bf16 P or V alone would inject ~0.4% into y).
// ---------------------------------------------------------------------------
__device__ __forceinline__ uint32_t packbf(float a, float b) {
    __nv_bfloat162 t = __floats2bfloat162_rn(a, b);
    return *(uint32_t*)&t;
}
__device__ __forceinline__ void hilo2(float a, float b, uint32_t& hi, uint32_t& lo) {
    __nv_bfloat16 ah = __float2bfloat16_rn(a), bh = __float2bfloat16_rn(b);
    __nv_bfloat162 h2; h2.x = ah; h2.y = bh;
    hi = *(uint32_t*)&h2;
    __nv_bfloat162 l2;
    l2.x = __float2bfloat16_rn(a - __bfloat162float(ah));
    l2.y = __float2bfloat16_rn(b - __bfloat162float(bh));
    lo = *(uint32_t*)&l2;
}

#define VSTRIDE 72   // bf16 stride: word stride 36 == 4 mod 32 -> conflict-free frag reads

__global__ __launch_bounds__(256) void flash_hmma_kernel(
    const float* __restrict__ qkv, float* __restrict__ att)
{
    __shared__ __nv_bfloat16 Ks[64][VSTRIDE];    // [key][d]
    __shared__ __nv_bfloat16 Vthi[64][VSTRIDE];  // [d][key] transposed hi
    __shared__ __nv_bfloat16 Vtlo[64][VSTRIDE];  // [d][key] transposed lo

    const int tid  = threadIdx.x;
    const int lane = tid & 31;
    const int wid  = tid >> 5;
    const int gid  = lane >> 2;
    const int tig  = lane & 3;
    const int qt = blockIdx.x, h = blockIdx.y, b = blockIdx.z;

    const int r0  = qt * 128 + wid * 16;
    const int rg0 = r0 + gid;
    const int rg1 = r0 + gid + 8;

    // ---- Q a-frags in registers (scaled by 1/8, bf16) ----
    const float* q0 = qkv + (size_t)(b * SEQ + rg0) * QKV_N + h * HD;
    const float* q1 = qkv + (size_t)(b * SEQ + rg1) * QKV_N + h * HD;
    uint32_t qa[4][4];
#pragma unroll
    for (int ks = 0; ks < 4; ks++) {
        int c = 16 * ks + 2 * tig;
        float2 t00 = *(const float2*)(q0 + c);
        float2 t10 = *(const float2*)(q1 + c);
        float2 t01 = *(const float2*)(q0 + c + 8);
        float2 t11 = *(const float2*)(q1 + c + 8);
        qa[ks][0] = packbf(t00.x * 0.125f, t00.y * 0.125f);
        qa[ks][1] = packbf(t10.x * 0.125f, t10.y * 0.125f);
        qa[ks][2] = packbf(t01.x * 0.125f, t01.y * 0.125f);
        qa[ks][3] = packbf(t11.x * 0.125f, t11.y * 0.125f);
    }

    float o[8][4];
#pragma unroll
    for (int dt = 0; dt < 8; dt++)
#pragma unroll
        for (int v = 0; v < 4; v++) o[dt][v] = 0.f;
    float m0 = -1e30f, m1 = -1e30f, l0 = 0.f, l1 = 0.f;

    const int ktmax = 2 * qt + 2;

    for (int kt = 0; kt < ktmax; kt++) {
        __syncthreads();   // all warps done reading previous tile

        // ---- K tile load: Ks[key][d] ----
        {
            int key = tid >> 2;
            int d0  = (tid & 3) * 16;
            const float* src = qkv + (size_t)(b * SEQ + kt * 64 + key) * QKV_N + CH + h * HD + d0;
#pragma unroll
            for (int j = 0; j < 4; j++) {
                float4 v = *(const float4*)(src + 4 * j);
                *(uint32_t*)&Ks[key][d0 + 4 * j]     = packbf(v.x, v.y);
                *(uint32_t*)&Ks[key][d0 + 4 * j + 2] = packbf(v.z, v.w);
            }
        }
        // ---- V tile load, transposed + hi/lo split: Vt*[d][key] ----
        {
            const float* vb = qkv + (size_t)(b * SEQ + kt * 64) * QKV_N + 2 * CH + h * HD;
#pragma unroll
            for (int i = 0; i < 2; i++) {
                int d0 = (wid + 8 * i) * 4;
                int kp = lane;
                const float* s0 = vb + (size_t)(2 * kp) * QKV_N + d0;
                const float* s1 = s0 + QKV_N;
                float4 v0 = *(const float4*)s0;
                float4 v1 = *(const float4*)s1;
                uint32_t hi, lo;
                hilo2(v0.x, v1.x, hi, lo);
                *(uint32_t*)&Vthi[d0 + 0][2 * kp] = hi; *(uint32_t*)&Vtlo[d0 + 0][2 * kp] = lo;
                hilo2(v0.y, v1.y, hi, lo);
                *(uint32_t*)&Vthi[d0 + 1][2 * kp] = hi; *(uint32_t*)&Vtlo[d0 + 1][2 * kp] = lo;
                hilo2(v0.z, v1.z, hi, lo);
                *(uint32_t*)&Vthi[d0 + 2][2 * kp] = hi; *(uint32_t*)&Vtlo[d0 + 2][2 * kp] = lo;
                hilo2(v0.w, v1.w, hi, lo);
                *(uint32_t*)&Vthi[d0 + 3][2 * kp] = hi; *(uint32_t*)&Vtlo[d0 + 3][2 * kp] = lo;
            }
        }
        __syncthreads();   // tile visible to all warps

        if (64 * kt <= r0 + 15) {   // warp has at least one valid key in this tile
            // ---- S = Q @ K^T ----
            float s[8][4];
#pragma unroll
            for (int nt = 0; nt < 8; nt++)
#pragma unroll
                for (int v = 0; v < 4; v++) s[nt][v] = 0.f;
#pragma unroll
            for (int nt = 0; nt < 8; nt++) {
                int krow = 8 * nt + gid;
#pragma unroll
                for (int ks = 0; ks < 4; ks++) {
                    uint32_t kb[2] = {
                        *(const uint32_t*)&Ks[krow][2 * tig + 16 * ks],
                        *(const uint32_t*)&Ks[krow][2 * tig + 8 + 16 * ks] };
                    MMA_BF16(s[nt], qa[ks], kb);
                }
            }
            // ---- causal mask ----
            if (64 * kt + 63 > r0) {
#pragma unroll
                for (int nt = 0; nt < 8; nt++) {
                    int k0 = 64 * kt + 8 * nt + 2 * tig;
                    if (k0     > rg0) s[nt][0] = -1e30f;
                    if (k0 + 1 > rg0) s[nt][1] = -1e30f;
                    if (k0     > rg1) s[nt][2] = -1e30f;
                    if (k0 + 1 > rg1) s[nt][3] = -1e30f;
                }
            }
            // ---- online softmax ----
            float tm0 = -1e30f, tm1 = -1e30f;
#pragma unroll
            for (int nt = 0; nt < 8; nt++) {
                tm0 = fmaxf(tm0, fmaxf(s[nt][0], s[nt][1]));
                tm1 = fmaxf(tm1, fmaxf(s[nt][2], s[nt][3]));
            }
            tm0 = fmaxf(tm0, __shfl_xor_sync(0xffffffffu, tm0, 1));
            tm0 = fmaxf(tm0, __shfl_xor_sync(0xffffffffu, tm0, 2));
            tm1 = fmaxf(tm1, __shfl_xor_sync(0xffffffffu, tm1, 1));
            tm1 = fmaxf(tm1, __shfl_xor_sync(0xffffffffu, tm1, 2));
            float mn0 = fmaxf(m0, tm0), mn1 = fmaxf(m1, tm1);
            float corr0 = __expf(m0 - mn0), corr1 = __expf(m1 - mn1);
            float valid0 = mn0 > -1e29f ? 1.f : 0.f;
            float valid1 = mn1 > -1e29f ? 1.f : 0.f;
            float ps0 = 0.f, ps1 = 0.f;
#pragma unroll
            for (int nt = 0; nt < 8; nt++) {
                s[nt][0] = __expf(s[nt][0] - mn0) * valid0;
                s[nt][1] = __expf(s[nt][1] - mn0) * valid0;
                s[nt][2] = __expf(s[nt][2] - mn1) * valid1;
                s[nt][3] = __expf(s[nt][3] - mn1) * valid1;
                ps0 += s[nt][0] + s[nt][1];
                ps1 += s[nt][2] + s[nt][3];
            }
            ps0 += __shfl_xor_sync(0xffffffffu, ps0, 1);
            ps0 += __shfl_xor_sync(0xffffffffu, ps0, 2);
            ps1 += __shfl_xor_sync(0xffffffffu, ps1, 1);
            ps1 += __shfl_xor_sync(0xffffffffu, ps1, 2);
            l0 = l0 * corr0 + ps0;
            l1 = l1 * corr1 + ps1;
            m0 = mn0; m1 = mn1;
#pragma unroll
            for (int dt = 0; dt < 8; dt++) {
                o[dt][0] *= corr0; o[dt][1] *= corr0;
                o[dt][2] *= corr1; o[dt][3] *= corr1;
            }
            // ---- O += P @ V (hi/lo 3-product) ----
#pragma unroll
            for (int at = 0; at < 4; at++) {
                uint32_t ph[4], pl[4];
                hilo2(s[2 * at][0],     s[2 * at][1],     ph[0], pl[0]);
                hilo2(s[2 * at][2],     s[2 * at][3],     ph[1], pl[1]);
                hilo2(s[2 * at + 1][0], s[2 * at + 1][1], ph[2], pl[2]);
                hilo2(s[2 * at + 1][2], s[2 * at + 1][3], ph[3], pl[3]);
#pragma unroll
                for (int dt = 0; dt < 8; dt++) {
                    int vr = 8 * dt + gid;
                    uint32_t bh[2] = {
                        *(const uint32_t*)&Vthi[vr][2 * tig + 16 * at],
                        *(const uint32_t*)&Vthi[vr][2 * tig + 8 + 16 * at] };
                    uint32_t bl[2] = {
                        *(const uint32_t*)&Vtlo[vr][2 * tig + 16 * at],
                        *(const uint32_t*)&Vtlo[vr][2 * tig + 8 + 16 * at] };
                    MMA_BF16(o[dt], ph, bh);
                    MMA_BF16(o[dt], pl, bh);
                    MMA_BF16(o[dt], ph, bl);
                }
            }
        }
    }

    // ---- normalize + store ----
    const float i0 = 1.f / l0, i1 = 1.f / l1;
    float* a0 = att + (size_t)(b * SEQ + rg0) * CH + h * HD;
    float* a1 = att + (size_t)(b * SEQ + rg1) * CH + h * HD;
#pragma unroll
    for (int dt = 0; dt < 8; dt++) {
        int d = 8 * dt + 2 * tig;
        float2 r0v, r1v;
        r0v.x = o[dt][0] * i0; r0v.y = o[dt][1] * i0;
        r1v.x = o[dt][2] * i1; r1v.y = o[dt][3] * i1;
        *(float2*)(a0 + d) = r0v;
        *(float2*)(a1 + d) = r1v;
    }
}

// ---------------------------------------------------------------------------
extern "C" void kernel_launch(void* const* d_in, const int* in_sizes, int n_in,
                              void* d_out, int out_size)
{
    const float* x      = (const float*)d_in[0];
    const float* w_attn = (const float*)d_in[1];
    const float* b_attn = (const float*)d_in[2];
    const float* w_proj = (const float*)d_in[3];
    const float* b_proj = (const float*)d_in[4];
    float* out = (float*)d_out;

    float *qkv, *att;
    __nv_bfloat16 *xhi, *xlo, *ahi, *alo, *wathi, *watlo, *wphi, *wplo;
    cudaGetSymbolAddress((void**)&qkv, g_qkv);
    cudaGetSymbolAddress((void**)&att, g_att);
    cudaGetSymbolAddress((void**)&xhi, g_xhi);
    cudaGetSymbolAddress((void**)&xlo, g_xlo);
    cudaGetSymbolAddress((void**)&ahi, g_ahi);
    cudaGetSymbolAddress((void**)&alo, g_alo);
    cudaGetSymbolAddress((void**)&wathi, g_wathi);
    cudaGetSymbolAddress((void**)&watlo, g_watlo);
    cudaGetSymbolAddress((void**)&wphi, g_wphi);
    cudaGetSymbolAddress((void**)&wplo, g_wplo);

    cudaFuncSetAttribute(hmma_gemm_kernel, cudaFuncAttributeMaxDynamicSharedMemorySize, GEMM_SMEM_H);

    // prep: split x; transpose+split weights
    split_kernel<<<(M_ROWS * CH) / 1024, 256>>>(x, xhi, xlo, M_ROWS * CH);
    transpose_split_kernel<<<(CH * QKV_N + 255) / 256, 256>>>(w_attn, wathi, watlo, CH, QKV_N);
    transpose_split_kernel<<<(CH * CH + 255) / 256, 256>>>(w_proj, wphi, wplo, CH, CH);

    // 1) QKV GEMM (HMMA): [8192,768] @ [768,2304]
    {
        dim3 grid(QKV_N / 128, M_ROWS / 128);
        hmma_gemm_kernel<<<grid, 256, GEMM_SMEM_H>>>(xhi, xlo, wathi, watlo, b_attn, qkv,
                                                     M_ROWS, QKV_N, CH);
    }

    // 2) Flash attention (HMMA)
    {
        dim3 grid(SEQ / 128, NH, BATCH);
        flash_hmma_kernel<<<grid, 256>>>(qkv, att);
    }

    // 3) split att, then proj GEMM (HMMA): [8192,768] @ [768,768]
    split_kernel<<<(M_ROWS * CH) / 1024, 256>>>(att, ahi, alo, M_ROWS * CH);
    {
        dim3 grid(CH / 128, M_ROWS / 128);
        hmma_gemm_kernel<<<grid, 256, GEMM_SMEM_H>>>(ahi, alo, wphi, wplo, b_proj, out,
                                                     M_ROWS, CH, CH);
    }
}

// round 17
// speedup vs baseline: 4.7785x; 1.0503x over previous
#include <cuda_runtime.h>
#include <cuda_bf16.h>
#include <cstdint>

// GPT-2 small attention: x[1,8,1024,768], w_attn[768,2304], w_proj[768,768]
#define BATCH 8
#define SEQ   1024
#define CH    768
#define NH    12
#define HD    64
#define M_ROWS (BATCH * SEQ)      // 8192
#define QKV_N (3 * CH)            // 2304

// ---------------- scratch (__device__ globals; no allocs allowed) ----------
__device__ float g_qkv[M_ROWS * QKV_N];
__device__ float g_att[M_ROWS * CH];
__device__ __nv_bfloat16 g_xhi[M_ROWS * CH];
__device__ __nv_bfloat16 g_xlo[M_ROWS * CH];
__device__ __nv_bfloat16 g_ahi[M_ROWS * CH];
__device__ __nv_bfloat16 g_alo[M_ROWS * CH];
__device__ __nv_bfloat16 g_wathi[QKV_N * CH];   // w_attn^T [2304,768]
__device__ __nv_bfloat16 g_watlo[QKV_N * CH];
__device__ __nv_bfloat16 g_wphi[CH * CH];       // w_proj^T [768,768]
__device__ __nv_bfloat16 g_wplo[CH * CH];

// ---------------------------------------------------------------------------
// Prep kernels: fp32 -> bf16 hi/lo split (and transposed variant for weights)
// ---------------------------------------------------------------------------
__global__ void split_kernel(const float* __restrict__ src,
                             __nv_bfloat16* __restrict__ hi, __nv_bfloat16* __restrict__ lo, int n) {
    int i = (blockIdx.x * 256 + threadIdx.x) * 4;
    if (i >= n) return;
    float4 v = *(const float4*)(src + i);
    __nv_bfloat16 h0 = __float2bfloat16_rn(v.x), h1 = __float2bfloat16_rn(v.y);
    __nv_bfloat16 h2 = __float2bfloat16_rn(v.z), h3 = __float2bfloat16_rn(v.w);
    hi[i + 0] = h0; hi[i + 1] = h1; hi[i + 2] = h2; hi[i + 3] = h3;
    lo[i + 0] = __float2bfloat16_rn(v.x - __bfloat162float(h0));
    lo[i + 1] = __float2bfloat16_rn(v.y - __bfloat162float(h1));
    lo[i + 2] = __float2bfloat16_rn(v.z - __bfloat162float(h2));
    lo[i + 3] = __float2bfloat16_rn(v.w - __bfloat162float(h3));
}

// w[K,N] -> wT hi/lo [N,K]
__global__ void transpose_split_kernel(const float* __restrict__ w,
                                       __nv_bfloat16* __restrict__ thi, __nv_bfloat16* __restrict__ tlo,
                                       int K, int N) {
    int idx = blockIdx.x * 256 + threadIdx.x;    // idx = n*K + k
    if (idx >= K * N) return;
    int n = idx / K, k = idx % K;
    float v = w[(size_t)k * N + n];
    __nv_bfloat16 h = __float2bfloat16_rn(v);
    thi[idx] = h;
    tlo[idx] = __float2bfloat16_rn(v - __bfloat162float(h));
}

// ---------------------------------------------------------------------------
// HMMA GEMM v2: 512 threads (16 warps, 4x4 grid, 32x32 warp tile),
// cp.async double-buffered loads, product-outer MMA ordering for ILP.
// C[M,N] = Ahi@Bhi^T + Ahi@Blo^T + Alo@Bhi^T + bias
// Fragment/bank layout identical to the R12-verified kernel (ROWP=40).
// ---------------------------------------------------------------------------
#define KCHUNK 32
#define ROWP   40                               // padded row stride (halves)
#define ARR_B  (128 * ROWP * 2)                 // 10240 bytes per array chunk
#define BUFH_B (4 * ARR_B)                      // Ahi, Alo, Bhi, Blo = 40960
#define GEMM_SMEM_H (2 * BUFH_B)                // double buffered = 81920

#define MMA_BF16(c, a, b)                                                      \
    asm volatile("mma.sync.aligned.m16n8k16.row.col.f32.bf16.bf16.f32 "        \
                 "{%0,%1,%2,%3}, {%4,%5,%6,%7}, {%8,%9}, {%0,%1,%2,%3};"       \
                 : "+f"((c)[0]), "+f"((c)[1]), "+f"((c)[2]), "+f"((c)[3])      \
                 : "r"((a)[0]), "r"((a)[1]), "r"((a)[2]), "r"((a)[3]),         \
                   "r"((b)[0]), "r"((b)[1]))

#define CP_ASYNC16(dst, src) \
    asm volatile("cp.async.cg.shared.global [%0], [%1], 16;" :: "r"(dst), "l"(src))
#define CP_COMMIT() asm volatile("cp.async.commit_group;" ::: "memory")
#define CP_WAIT1()  asm volatile("cp.async.wait_group 1;" ::: "memory")
#define CP_WAIT0()  asm volatile("cp.async.wait_group 0;" ::: "memory")

__device__ __forceinline__ uint32_t smem_addr_u32(const void* p) {
    uint32_t a;
    asm("{ .reg .u64 t; cvta.to.shared.u64 t, %1; cvt.u32.u64 %0, t; }" : "=r"(a) : "l"(p));
    return a;
}

__global__ __launch_bounds__(512, 1) void hmma_gemm_kernel(
    const __nv_bfloat16* __restrict__ Ahi, const __nv_bfloat16* __restrict__ Alo,
    const __nv_bfloat16* __restrict__ Bhi, const __nv_bfloat16* __restrict__ Blo,
    const float* __restrict__ bias, float* __restrict__ C, int M, int N, int K)
{
    extern __shared__ char smem[];
    const uint32_t sbase = smem_addr_u32(smem);
    const int tid  = threadIdx.x;
    const int lane = tid & 31;
    const int wid  = tid >> 5;
    const int wm   = wid >> 2;          // 0..3 (M dimension)
    const int wn   = wid & 3;           // 0..3 (N dimension)
    const int gid  = lane >> 2;         // 0..7
    const int tig  = lane & 3;          // 0..3
    const int m0 = blockIdx.y * 128;
    const int n0 = blockIdx.x * 128;
    const int nch = K / KCHUNK;

    float acc[2][4][4];
#pragma unroll
    for (int i = 0; i < 2; i++)
#pragma unroll
        for (int j = 0; j < 4; j++)
#pragma unroll
            for (int v = 0; v < 4; v++) acc[i][j][v] = 0.f;

    const __nv_bfloat16* srcs[4] = { Ahi + (size_t)m0 * K, Alo + (size_t)m0 * K,
                                     Bhi + (size_t)n0 * K, Blo + (size_t)n0 * K };
    // per-thread load coords: 512 threads cover 128 rows x 4 16B-units per array
    const int lr = tid >> 2;            // row 0..127
    const int lc = tid & 3;             // 16B unit 0..3

#define ISSUE_CHUNK(kc, p) do {                                                \
    _Pragma("unroll")                                                          \
    for (int t = 0; t < 4; t++) {                                              \
        uint32_t dst = sbase + (p) * BUFH_B + t * ARR_B + lr * (ROWP * 2) + lc * 16; \
        const void* s = srcs[t] + (size_t)lr * K + (kc) * KCHUNK + lc * 8;     \
        CP_ASYNC16(dst, s);                                                    \
    }                                                                          \
    CP_COMMIT();                                                               \
} while (0)

    ISSUE_CHUNK(0, 0);

    for (int kc = 0; kc < nch; kc++) {
        const int p = kc & 1;
        if (kc + 1 < nch) { ISSUE_CHUNK(kc + 1, p ^ 1); CP_WAIT1(); }
        else              { CP_WAIT0(); }
        __syncthreads();

        const __nv_bfloat16* Ah = (const __nv_bfloat16*)(smem + p * BUFH_B);
        const __nv_bfloat16* Al = (const __nv_bfloat16*)(smem + p * BUFH_B + ARR_B);
        const __nv_bfloat16* Bh = (const __nv_bfloat16*)(smem + p * BUFH_B + 2 * ARR_B);
        const __nv_bfloat16* Bl = (const __nv_bfloat16*)(smem + p * BUFH_B + 3 * ARR_B);

#pragma unroll
        for (int ks = 0; ks < 2; ks++) {
            const int c = ks * 16 + 2 * tig;
            uint32_t ah[2][4], al[2][4];
#pragma unroll
            for (int tm = 0; tm < 2; tm++) {
                int r = wm * 32 + tm * 16 + gid;
                ah[tm][0] = *(const uint32_t*)(Ah + r * ROWP + c);
                ah[tm][1] = *(const uint32_t*)(Ah + (r + 8) * ROWP + c);
                ah[tm][2] = *(const uint32_t*)(Ah + r * ROWP + c + 8);
                ah[tm][3] = *(const uint32_t*)(Ah + (r + 8) * ROWP + c + 8);
                al[tm][0] = *(const uint32_t*)(Al + r * ROWP + c);
                al[tm][1] = *(const uint32_t*)(Al + (r + 8) * ROWP + c);
                al[tm][2] = *(const uint32_t*)(Al + r * ROWP + c + 8);
                al[tm][3] = *(const uint32_t*)(Al + (r + 8) * ROWP + c + 8);
            }
            uint32_t bh[4][2], bl[4][2];
#pragma unroll
            for (int tn = 0; tn < 4; tn++) {
                int nr = wn * 32 + tn * 8 + gid;
                bh[tn][0] = *(const uint32_t*)(Bh + nr * ROWP + c);
                bh[tn][1] = *(const uint32_t*)(Bh + nr * ROWP + c + 8);
                bl[tn][0] = *(const uint32_t*)(Bl + nr * ROWP + c);
                bl[tn][1] = *(const uint32_t*)(Bl + nr * ROWP + c + 8);
            }
            // product-outer: 8 independent acc chains between reuses
#pragma unroll
            for (int tm = 0; tm < 2; tm++)
#pragma unroll
                for (int tn = 0; tn < 4; tn++)
                    MMA_BF16(acc[tm][tn], ah[tm], bh[tn]);
#pragma unroll
            for (int tm = 0; tm < 2; tm++)
#pragma unroll
                for (int tn = 0; tn < 4; tn++)
                    MMA_BF16(acc[tm][tn], ah[tm], bl[tn]);
#pragma unroll
            for (int tm = 0; tm < 2; tm++)
#pragma unroll
                for (int tn = 0; tn < 4; tn++)
                    MMA_BF16(acc[tm][tn], al[tm], bh[tn]);
        }
        __syncthreads();
    }

    // ---- epilogue: bias + store ----
#pragma unroll
    for (int tm = 0; tm < 2; tm++) {
        int r = m0 + wm * 32 + tm * 16 + gid;
#pragma unroll
        for (int tn = 0; tn < 4; tn++) {
            int n = n0 + wn * 32 + tn * 8 + 2 * tig;
            float2 bv = *(const float2*)(bias + n);
            float2 lo, hi2;
            lo.x = acc[tm][tn][0] + bv.x;
            lo.y = acc[tm][tn][1] + bv.y;
            hi2.x = acc[tm][tn][2] + bv.x;
            hi2.y = acc[tm][tn][3] + bv.y;
            *(float2*)(C + (size_t)r * N + n) = lo;
            *(float2*)(C + (size_t)(r + 8) * N + n) = hi2;
        }
    }
}

// ---------------------------------------------------------------------------
// Flash attention on HMMA (UNCHANGED — hardware-verified in R15)
// ---------------------------------------------------------------------------
__device__ __forceinline__ uint32_t packbf(float a, float b) {
    __nv_bfloat162 t = __floats2bfloat162_rn(a, b);
    return *(uint32_t*)&t;
}
__device__ __forceinline__ void hilo2(float a, float b, uint32_t& hi, uint32_t& lo) {
    __nv_bfloat16 ah = __float2bfloat16_rn(a), bh = __float2bfloat16_rn(b);
    __nv_bfloat162 h2; h2.x = ah; h2.y = bh;
    hi = *(uint32_t*)&h2;
    __nv_bfloat162 l2;
    l2.x = __float2bfloat16_rn(a - __bfloat162float(ah));
    l2.y = __float2bfloat16_rn(b - __bfloat162float(bh));
    lo = *(uint32_t*)&l2;
}

#define VSTRIDE 72   // bf16 stride: word stride 36 == 4 mod 32 -> conflict-free frag reads

__global__ __launch_bounds__(256) void flash_hmma_kernel(
    const float* __restrict__ qkv, float* __restrict__ att)
{
    __shared__ __nv_bfloat16 Ks[64][VSTRIDE];    // [key][d]
    __shared__ __nv_bfloat16 Vthi[64][VSTRIDE];  // [d][key] transposed hi
    __shared__ __nv_bfloat16 Vtlo[64][VSTRIDE];  // [d][key] transposed lo

    const int tid  = threadIdx.x;
    const int lane = tid & 31;
    const int wid  = tid >> 5;
    const int gid  = lane >> 2;
    const int tig  = lane & 3;
    const int qt = blockIdx.x, h = blockIdx.y, b = blockIdx.z;

    const int r0  = qt * 128 + wid * 16;
    const int rg0 = r0 + gid;
    const int rg1 = r0 + gid + 8;

    const float* q0 = qkv + (size_t)(b * SEQ + rg0) * QKV_N + h * HD;
    const float* q1 = qkv + (size_t)(b * SEQ + rg1) * QKV_N + h * HD;
    uint32_t qa[4][4];
#pragma unroll
    for (int ks = 0; ks < 4; ks++) {
        int c = 16 * ks + 2 * tig;
        float2 t00 = *(const float2*)(q0 + c);
        float2 t10 = *(const float2*)(q1 + c);
        float2 t01 = *(const float2*)(q0 + c + 8);
        float2 t11 = *(const float2*)(q1 + c + 8);
        qa[ks][0] = packbf(t00.x * 0.125f, t00.y * 0.125f);
        qa[ks][1] = packbf(t10.x * 0.125f, t10.y * 0.125f);
        qa[ks][2] = packbf(t01.x * 0.125f, t01.y * 0.125f);
        qa[ks][3] = packbf(t11.x * 0.125f, t11.y * 0.125f);
    }

    float o[8][4];
#pragma unroll
    for (int dt = 0; dt < 8; dt++)
#pragma unroll
        for (int v = 0; v < 4; v++) o[dt][v] = 0.f;
    float m0 = -1e30f, m1 = -1e30f, l0 = 0.f, l1 = 0.f;

    const int ktmax = 2 * qt + 2;

    for (int kt = 0; kt < ktmax; kt++) {
        __syncthreads();

        {
            int key = tid >> 2;
            int d0  = (tid & 3) * 16;
            const float* src = qkv + (size_t)(b * SEQ + kt * 64 + key) * QKV_N + CH + h * HD + d0;
#pragma unroll
            for (int j = 0; j < 4; j++) {
                float4 v = *(const float4*)(src + 4 * j);
                *(uint32_t*)&Ks[key][d0 + 4 * j]     = packbf(v.x, v.y);
                *(uint32_t*)&Ks[key][d0 + 4 * j + 2] = packbf(v.z, v.w);
            }
        }
        {
            const float* vb = qkv + (size_t)(b * SEQ + kt * 64) * QKV_N + 2 * CH + h * HD;
#pragma unroll
            for (int i = 0; i < 2; i++) {
                int d0 = (wid + 8 * i) * 4;
                int kp = lane;
                const float* s0 = vb + (size_t)(2 * kp) * QKV_N + d0;
                const float* s1 = s0 + QKV_N;
                float4 v0 = *(const float4*)s0;
                float4 v1 = *(const float4*)s1;
                uint32_t hi, lo;
                hilo2(v0.x, v1.x, hi, lo);
                *(uint32_t*)&Vthi[d0 + 0][2 * kp] = hi; *(uint32_t*)&Vtlo[d0 + 0][2 * kp] = lo;
                hilo2(v0.y, v1.y, hi, lo);
                *(uint32_t*)&Vthi[d0 + 1][2 * kp] = hi; *(uint32_t*)&Vtlo[d0 + 1][2 * kp] = lo;
                hilo2(v0.z, v1.z, hi, lo);
                *(uint32_t*)&Vthi[d0 + 2][2 * kp] = hi; *(uint32_t*)&Vtlo[d0 + 2][2 * kp] = lo;
                hilo2(v0.w, v1.w, hi, lo);
                *(uint32_t*)&Vthi[d0 + 3][2 * kp] = hi; *(uint32_t*)&Vtlo[d0 + 3][2 * kp] = lo;
            }
        }
        __syncthreads();

        if (64 * kt <= r0 + 15) {
            float s[8][4];
#pragma unroll
            for (int nt = 0; nt < 8; nt++)
#pragma unroll
                for (int v = 0; v < 4; v++) s[nt][v] = 0.f;
#pragma unroll
            for (int nt = 0; nt < 8; nt++) {
                int krow = 8 * nt + gid;
#pragma unroll
                for (int ks = 0; ks < 4; ks++) {
                    uint32_t kb[2] = {
                        *(const uint32_t*)&Ks[krow][2 * tig + 16 * ks],
                        *(const uint32_t*)&Ks[krow][2 * tig + 8 + 16 * ks] };
                    MMA_BF16(s[nt], qa[ks], kb);
                }
            }
            if (64 * kt + 63 > r0) {
#pragma unroll
                for (int nt = 0; nt < 8; nt++) {
                    int k0 = 64 * kt + 8 * nt + 2 * tig;
                    if (k0     > rg0) s[nt][0] = -1e30f;
                    if (k0 + 1 > rg0) s[nt][1] = -1e30f;
                    if (k0     > rg1) s[nt][2] = -1e30f;
                    if (k0 + 1 > rg1) s[nt][3] = -1e30f;
                }
            }
            float tm0 = -1e30f, tm1 = -1e30f;
#pragma unroll
            for (int nt = 0; nt < 8; nt++) {
                tm0 = fmaxf(tm0, fmaxf(s[nt][0], s[nt][1]));
                tm1 = fmaxf(tm1, fmaxf(s[nt][2], s[nt][3]));
            }
            tm0 = fmaxf(tm0, __shfl_xor_sync(0xffffffffu, tm0, 1));
            tm0 = fmaxf(tm0, __shfl_xor_sync(0xffffffffu, tm0, 2));
            tm1 = fmaxf(tm1, __shfl_xor_sync(0xffffffffu, tm1, 1));
            tm1 = fmaxf(tm1, __shfl_xor_sync(0xffffffffu, tm1, 2));
            float mn0 = fmaxf(m0, tm0), mn1 = fmaxf(m1, tm1);
            float corr0 = __expf(m0 - mn0), corr1 = __expf(m1 - mn1);
            float valid0 = mn0 > -1e29f ? 1.f : 0.f;
            float valid1 = mn1 > -1e29f ? 1.f : 0.f;
            float ps0 = 0.f, ps1 = 0.f;
#pragma unroll
            for (int nt = 0; nt < 8; nt++) {
                s[nt][0] = __expf(s[nt][0] - mn0) * valid0;
                s[nt][1] = __expf(s[nt][1] - mn0) * valid0;
                s[nt][2] = __expf(s[nt][2] - mn1) * valid1;
                s[nt][3] = __expf(s[nt][3] - mn1) * valid1;
                ps0 += s[nt][0] + s[nt][1];
                ps1 += s[nt][2] + s[nt][3];
            }
            ps0 += __shfl_xor_sync(0xffffffffu, ps0, 1);
            ps0 += __shfl_xor_sync(0xffffffffu, ps0, 2);
            ps1 += __shfl_xor_sync(0xffffffffu, ps1, 1);
            ps1 += __shfl_xor_sync(0xffffffffu, ps1, 2);
            l0 = l0 * corr0 + ps0;
            l1 = l1 * corr1 + ps1;
            m0 = mn0; m1 = mn1;
#pragma unroll
            for (int dt = 0; dt < 8; dt++) {
                o[dt][0] *= corr0; o[dt][1] *= corr0;
                o[dt][2] *= corr1; o[dt][3] *= corr1;
            }
#pragma unroll
            for (int at = 0; at < 4; at++) {
                uint32_t ph[4], pl[4];
                hilo2(s[2 * at][0],     s[2 * at][1],     ph[0], pl[0]);
                hilo2(s[2 * at][2],     s[2 * at][3],     ph[1], pl[1]);
                hilo2(s[2 * at + 1][0], s[2 * at + 1][1], ph[2], pl[2]);
                hilo2(s[2 * at + 1][2], s[2 * at + 1][3], ph[3], pl[3]);
#pragma unroll
                for (int dt = 0; dt < 8; dt++) {
                    int vr = 8 * dt + gid;
                    uint32_t bh[2] = {
                        *(const uint32_t*)&Vthi[vr][2 * tig + 16 * at],
                        *(const uint32_t*)&Vthi[vr][2 * tig + 8 + 16 * at] };
                    uint32_t bl[2] = {
                        *(const uint32_t*)&Vtlo[vr][2 * tig + 16 * at],
                        *(const uint32_t*)&Vtlo[vr][2 * tig + 8 + 16 * at] };
                    MMA_BF16(o[dt], ph, bh);
                    MMA_BF16(o[dt], pl, bh);
                    MMA_BF16(o[dt], ph, bl);
                }
            }
        }
    }

    const float i0 = 1.f / l0, i1 = 1.f / l1;
    float* a0 = att + (size_t)(b * SEQ + rg0) * CH + h * HD;
    float* a1 = att + (size_t)(b * SEQ + rg1) * CH + h * HD;
#pragma unroll
    for (int dt = 0; dt < 8; dt++) {
        int d = 8 * dt + 2 * tig;
        float2 r0v, r1v;
        r0v.x = o[dt][0] * i0; r0v.y = o[dt][1] * i0;
        r1v.x = o[dt][2] * i1; r1v.y = o[dt][3] * i1;
        *(float2*)(a0 + d) = r0v;
        *(float2*)(a1 + d) = r1v;
    }
}

// ---------------------------------------------------------------------------
extern "C" void kernel_launch(void* const* d_in, const int* in_sizes, int n_in,
                              void* d_out, int out_size)
{
    const float* x      = (const float*)d_in[0];
    const float* w_attn = (const float*)d_in[1];
    const float* b_attn = (const float*)d_in[2];
    const float* w_proj = (const float*)d_in[3];
    const float* b_proj = (const float*)d_in[4];
    float* out = (float*)d_out;

    float *qkv, *att;
    __nv_bfloat16 *xhi, *xlo, *ahi, *alo, *wathi, *watlo, *wphi, *wplo;
    cudaGetSymbolAddress((void**)&qkv, g_qkv);
    cudaGetSymbolAddress((void**)&att, g_att);
    cudaGetSymbolAddress((void**)&xhi, g_xhi);
    cudaGetSymbolAddress((void**)&xlo, g_xlo);
    cudaGetSymbolAddress((void**)&ahi, g_ahi);
    cudaGetSymbolAddress((void**)&alo, g_alo);
    cudaGetSymbolAddress((void**)&wathi, g_wathi);
    cudaGetSymbolAddress((void**)&watlo, g_watlo);
    cudaGetSymbolAddress((void**)&wphi, g_wphi);
    cudaGetSymbolAddress((void**)&wplo, g_wplo);

    cudaFuncSetAttribute(hmma_gemm_kernel, cudaFuncAttributeMaxDynamicSharedMemorySize, GEMM_SMEM_H);

    // prep: split x; transpose+split weights
    split_kernel<<<(M_ROWS * CH) / 1024, 256>>>(x, xhi, xlo, M_ROWS * CH);
    transpose_split_kernel<<<(CH * QKV_N + 255) / 256, 256>>>(w_attn, wathi, watlo, CH, QKV_N);
    transpose_split_kernel<<<(CH * CH + 255) / 256, 256>>>(w_proj, wphi, wplo, CH, CH);

    // 1) QKV GEMM (HMMA): [8192,768] @ [768,2304]
    {
        dim3 grid(QKV_N / 128, M_ROWS / 128);
        hmma_gemm_kernel<<<grid, 512, GEMM_SMEM_H>>>(xhi, xlo, wathi, watlo, b_attn, qkv,
                                                     M_ROWS, QKV_N, CH);
    }

    // 2) Flash attention (HMMA)
    {
        dim3 grid(SEQ / 128, NH, BATCH);
        flash_hmma_kernel<<<grid, 256>>>(qkv, att);
    }

    // 3) split att, then proj GEMM (HMMA): [8192,768] @ [768,768]
    split_kernel<<<(M_ROWS * CH) / 1024, 256>>>(att, ahi, alo, M_ROWS * CH);
    {
        dim3 grid(CH / 128, M_ROWS / 128);
        hmma_gemm_kernel<<<grid, 512, GEMM_SMEM_H>>>(ahi, alo, wphi, wplo, b_proj, out,
                                                     M_ROWS, CH, CH);
    }
}